// round 3
// baseline (speedup 1.0000x reference)
#include <cuda_runtime.h>
#include <cuda_bf16.h>

#define NN 50000
#define EE 600000
#define ET (EE + NN)   // edges incl. self loops
#define HH 128
#define NEG 0.2f

// ---------------- device scratch (no allocs allowed) ----------------
// float4-typed to guarantee 16B alignment for vector accesses.
__device__ float4 g_hp4[NN * 32];     // layer projection h @ W^T
__device__ float4 g_hbuf4[NN * 32];   // layer-1 output (input to layer 2)
__device__ float  g_s[NN];            // hp . att_src
__device__ float  g_d[NN];            // hp . att_dst
__device__ int    g_cnt[NN];          // degree counts, then scatter cursors
__device__ int    g_off[NN + 1];      // CSR offsets by destination
__device__ int    g_csrc[ET];         // CSR: source node per slot
__device__ float  g_cea[ET];          // CSR: edge_attr scalar per slot
__device__ float  g_scal[4];          // [0]=mean(edge_attr) [1]=c0 [2]=c1
__device__ float  g_partial[256];     // mean reduction partials
__device__ int    g_blksum[256];      // scan block partials

// ---------------- setup: mean(edge_attr) and c = We . att_e ----------------
__global__ void mean_partial_k(const float* __restrict__ ea) {
    __shared__ float sm[256];
    float sum = 0.f;
    for (int i = blockIdx.x * 256 + threadIdx.x; i < EE; i += 256 * 256)
        sum += ea[i];
    sm[threadIdx.x] = sum;
    __syncthreads();
    for (int o = 128; o; o >>= 1) {
        if (threadIdx.x < o) sm[threadIdx.x] += sm[threadIdx.x + o];
        __syncthreads();
    }
    if (threadIdx.x == 0) g_partial[blockIdx.x] = sm[0];
}

__global__ void setup_scalars_k(const float* __restrict__ We0,
                                const float* __restrict__ ae0,
                                const float* __restrict__ We1,
                                const float* __restrict__ ae1) {
    __shared__ float sm[256];
    int t = threadIdx.x;
    sm[t] = g_partial[t];
    __syncthreads();
    for (int o = 128; o; o >>= 1) {
        if (t < o) sm[t] += sm[t + o];
        __syncthreads();
    }
    if (t == 0) g_scal[0] = sm[0] / (float)EE;
    __syncthreads();
    sm[t] = (t < HH) ? We0[t] * ae0[t] : 0.f;
    __syncthreads();
    for (int o = 128; o; o >>= 1) {
        if (t < o) sm[t] += sm[t + o];
        __syncthreads();
    }
    if (t == 0) g_scal[1] = sm[0];
    __syncthreads();
    sm[t] = (t < HH) ? We1[t] * ae1[t] : 0.f;
    __syncthreads();
    for (int o = 128; o; o >>= 1) {
        if (t < o) sm[t] += sm[t + o];
        __syncthreads();
    }
    if (t == 0) g_scal[2] = sm[0];
}

// ---------------- CSR build ----------------
__global__ void zero_cnt_k() {
    int i = blockIdx.x * blockDim.x + threadIdx.x;
    if (i < NN) g_cnt[i] = 0;
}

__global__ void count_k(const int* __restrict__ ei) {
    int e = blockIdx.x * blockDim.x + threadIdx.x;
    if (e >= ET) return;
    int dst = (e < EE) ? ei[EE + e] : (e - EE);
    atomicAdd(&g_cnt[dst], 1);
}

// per-chunk exclusive scan (chunk = 256)
__global__ void scan1_k() {
    __shared__ int sm[256];
    int t = threadIdx.x;
    int gi = blockIdx.x * 256 + t;
    int v = (gi < NN) ? g_cnt[gi] : 0;
    sm[t] = v;
    __syncthreads();
    for (int o = 1; o < 256; o <<= 1) {
        int add = (t >= o) ? sm[t - o] : 0;
        __syncthreads();
        sm[t] += add;
        __syncthreads();
    }
    if (gi < NN) g_off[gi] = sm[t] - v;   // exclusive within chunk
    if (t == 255) g_blksum[blockIdx.x] = sm[255];
}

__global__ void scan2_k(int nblk) {
    __shared__ int sm[256];
    int t = threadIdx.x;
    int v = (t < nblk) ? g_blksum[t] : 0;
    sm[t] = v;
    __syncthreads();
    for (int o = 1; o < 256; o <<= 1) {
        int add = (t >= o) ? sm[t - o] : 0;
        __syncthreads();
        sm[t] += add;
        __syncthreads();
    }
    g_blksum[t] = sm[t] - v;              // exclusive block bases
}

__global__ void scan3_k() {
    int gi = blockIdx.x * blockDim.x + threadIdx.x;
    if (gi < NN) {
        int off = g_off[gi] + g_blksum[gi >> 8];
        g_off[gi] = off;
        g_cnt[gi] = off;                  // becomes scatter cursor
    }
    if (gi == 0) g_off[NN] = ET;
}

__global__ void scatter_k(const int* __restrict__ ei,
                          const float* __restrict__ eattr) {
    int e = blockIdx.x * blockDim.x + threadIdx.x;
    if (e >= ET) return;
    int src, dst; float ea;
    if (e < EE) {
        src = ei[e];
        dst = ei[EE + e];
        ea = eattr[e];
    } else {
        src = dst = e - EE;
        ea = g_scal[0];
    }
    int pos = atomicAdd(&g_cnt[dst], 1);
    g_csrc[pos] = src;
    g_cea[pos] = ea;
}

// ---------------- GEMM: C[n][c] = sum_k A[n][k] * W[c][k]  (K=128,C=128) --------
__global__ void gemm_nt_k(const float* __restrict__ A_ext, int use_hbuf,
                          const float* __restrict__ W) {
    const float* __restrict__ A = use_hbuf ? (const float*)g_hbuf4 : A_ext;
    __shared__ float As[64][33];
    __shared__ float Ws[128][33];
    int tx = threadIdx.x;            // 256 threads
    int row0 = blockIdx.x * 64;
    int cx = tx & 31;
    int ry = tx >> 5;
    float acc[8][4] = {};
    for (int kt = 0; kt < 128; kt += 32) {
        for (int i = tx; i < 64 * 32; i += 256) {
            int r = i >> 5, k = i & 31;
            int gr = row0 + r;
            As[r][k] = (gr < NN) ? A[gr * 128 + kt + k] : 0.f;
        }
        for (int i = tx; i < 128 * 32; i += 256) {
            int c = i >> 5, k = i & 31;
            Ws[c][k] = W[c * 128 + kt + k];
        }
        __syncthreads();
#pragma unroll
        for (int k = 0; k < 32; k++) {
            float a[8], w[4];
#pragma unroll
            for (int i = 0; i < 8; i++) a[i] = As[ry * 8 + i][k];
#pragma unroll
            for (int j = 0; j < 4; j++) w[j] = Ws[cx * 4 + j][k];
#pragma unroll
            for (int i = 0; i < 8; i++)
#pragma unroll
                for (int j = 0; j < 4; j++) acc[i][j] += a[i] * w[j];
        }
        __syncthreads();
    }
#pragma unroll
    for (int i = 0; i < 8; i++) {
        int gr = row0 + ry * 8 + i;
        if (gr < NN)
            g_hp4[gr * 32 + cx] = make_float4(acc[i][0], acc[i][1], acc[i][2], acc[i][3]);
    }
}

// ---------------- per-node dot products with att_src / att_dst ----------------
__global__ void dots_k(const float* __restrict__ as, const float* __restrict__ ad) {
    int gid = blockIdx.x * blockDim.x + threadIdx.x;   // exact: NN*32 threads
    int n = gid >> 5, lane = gid & 31;
    float4 v = g_hp4[n * 32 + lane];
    float a0 = as[lane * 4 + 0], a1 = as[lane * 4 + 1],
          a2 = as[lane * 4 + 2], a3 = as[lane * 4 + 3];
    float b0 = ad[lane * 4 + 0], b1 = ad[lane * 4 + 1],
          b2 = ad[lane * 4 + 2], b3 = ad[lane * 4 + 3];
    float ps = v.x * a0 + v.y * a1 + v.z * a2 + v.w * a3;
    float pd = v.x * b0 + v.y * b1 + v.z * b2 + v.w * b3;
#pragma unroll
    for (int o = 16; o; o >>= 1) {
        ps += __shfl_down_sync(0xFFFFFFFFu, ps, o);
        pd += __shfl_down_sync(0xFFFFFFFFu, pd, o);
    }
    if (lane == 0) { g_s[n] = ps; g_d[n] = pd; }
}

// ---------------- warp-per-node softmax + aggregation (no atomics) ------------
__global__ void agg_k(const float* __restrict__ b, float* __restrict__ out,
                      int layer, int colbase4, int writeH) {
    int warp = (blockIdx.x * blockDim.x + threadIdx.x) >> 5;  // exact: NN warps
    int lane = threadIdx.x & 31;
    int n = warp;
    int beg = g_off[n], end = g_off[n + 1];
    float c = g_scal[1 + layer];
    float dterm = g_d[n];

    // pass 1: segment max (every node has a self loop -> nonempty)
    float m = -1e30f;
    for (int i = beg + lane; i < end; i += 32) {
        float a = g_s[g_csrc[i]] + dterm + c * g_cea[i];
        a = (a > 0.f) ? a : NEG * a;
        m = fmaxf(m, a);
    }
#pragma unroll
    for (int o = 16; o; o >>= 1) m = fmaxf(m, __shfl_xor_sync(0xFFFFFFFFu, m, o));

    // pass 2: exp weights + weighted feature gather
    float4 acc = make_float4(0.f, 0.f, 0.f, 0.f);
    float denom = 0.f;
    for (int i0 = beg; i0 < end; i0 += 32) {
        int i = i0 + lane;
        int src = 0; float w = 0.f;
        if (i < end) {
            src = g_csrc[i];
            float a = g_s[src] + dterm + c * g_cea[i];
            a = (a > 0.f) ? a : NEG * a;
            w = __expf(a - m);
            denom += w;
        }
        int nvalid = min(32, end - i0);
        for (int j = 0; j < nvalid; j++) {
            float wj = __shfl_sync(0xFFFFFFFFu, w, j);
            int sj = __shfl_sync(0xFFFFFFFFu, src, j);
            float4 v = g_hp4[sj * 32 + lane];
            acc.x += wj * v.x;
            acc.y += wj * v.y;
            acc.z += wj * v.z;
            acc.w += wj * v.w;
        }
    }
#pragma unroll
    for (int o = 16; o; o >>= 1) denom += __shfl_xor_sync(0xFFFFFFFFu, denom, o);

    float inv = 1.0f / (denom + 1e-16f);
    float bx = b[lane * 4 + 0], by = b[lane * 4 + 1],
          bz = b[lane * 4 + 2], bw = b[lane * 4 + 3];
    float ox = fmaxf(acc.x * inv + bx, 0.f);
    float oy = fmaxf(acc.y * inv + by, 0.f);
    float oz = fmaxf(acc.z * inv + bz, 0.f);
    float ow = fmaxf(acc.w * inv + bw, 0.f);
    int base = n * 384 + colbase4 * 4 + lane * 4;
    out[base + 0] = ox;
    out[base + 1] = oy;
    out[base + 2] = oz;
    out[base + 3] = ow;
    if (writeH) g_hbuf4[n * 32 + lane] = make_float4(ox, oy, oz, ow);
}

// ---------------- copy x into first 128 output columns ----------------
__global__ void copy_x_k(const float* __restrict__ x, float* __restrict__ out) {
    int i = blockIdx.x * blockDim.x + threadIdx.x;   // exact: NN*128 threads
    int n = i >> 7, q = i & 127;
    out[n * 384 + q] = x[i];
}

extern "C" void kernel_launch(void* const* d_in, const int* in_sizes, int n_in,
                              void* d_out, int out_size) {
    const float* x   = (const float*)d_in[0];
    const int*   ei  = (const int*)d_in[1];     // int32 [2, E] (JAX x64 disabled)
    const float* ea  = (const float*)d_in[2];
    const float* W0  = (const float*)d_in[3];
    const float* as0 = (const float*)d_in[4];
    const float* ad0 = (const float*)d_in[5];
    const float* We0 = (const float*)d_in[6];
    const float* ae0 = (const float*)d_in[7];
    const float* b0  = (const float*)d_in[8];
    const float* W1  = (const float*)d_in[9];
    const float* as1 = (const float*)d_in[10];
    const float* ad1 = (const float*)d_in[11];
    const float* We1 = (const float*)d_in[12];
    const float* ae1 = (const float*)d_in[13];
    const float* b1  = (const float*)d_in[14];
    float* out = (float*)d_out;

    const int T = 256;
    const int blkN32  = (NN * 32) / T;            // 6250 (exact)
    const int blkN128 = (NN * 128) / T;           // 25000 (exact)
    const int blkN    = (NN + T - 1) / T;         // 196
    const int blkE    = (ET + T - 1) / T;         // 2540
    const int blkG    = (NN + 63) / 64;           // 782

    copy_x_k<<<blkN128, T>>>(x, out);
    mean_partial_k<<<256, T>>>(ea);
    setup_scalars_k<<<1, T>>>(We0, ae0, We1, ae1);

    // CSR by destination
    zero_cnt_k<<<blkN, T>>>();
    count_k<<<blkE, T>>>(ei);
    scan1_k<<<blkN, T>>>();
    scan2_k<<<1, T>>>(blkN);
    scan3_k<<<blkN, T>>>();
    scatter_k<<<blkE, T>>>(ei, ea);

    // ---- layer 0 ----
    gemm_nt_k<<<blkG, T>>>(x, 0, W0);
    dots_k<<<blkN32, T>>>(as0, ad0);
    agg_k<<<blkN32, T>>>(b0, out, 0, 32, 1);

    // ---- layer 1 ----
    gemm_nt_k<<<blkG, T>>>(nullptr, 1, W1);
    dots_k<<<blkN32, T>>>(as1, ad1);
    agg_k<<<blkN32, T>>>(b1, out, 1, 64, 0);
}

// round 4
// speedup vs baseline: 1.4560x; 1.4560x over previous
#include <cuda_runtime.h>
#include <cuda_bf16.h>

#define NN 50000
#define EE 600000
#define ET (EE + NN)   // edges incl. self loops
#define HH 128
#define NEG 0.2f

// ---------------- device scratch (no allocs allowed) ----------------
__device__ float4 g_hp4[NN * 32];     // layer projection h @ W^T
__device__ float4 g_hbuf4[NN * 32];   // layer-1 output (input to layer 2)
__device__ float  g_s[NN];            // hp . att_src
__device__ float  g_d[NN];            // hp . att_dst
__device__ int    g_cnt[NN];          // degree counts, then scatter cursors
__device__ int    g_off[NN + 1];      // CSR offsets by destination
__device__ int    g_csrc[ET];         // CSR: source node per slot
__device__ float  g_cea[ET];          // CSR: edge_attr scalar per slot
__device__ float  g_scal[4];          // [0]=mean(edge_attr) [1]=c0 [2]=c1
__device__ float  g_partial[256];     // mean reduction partials
__device__ int    g_blksum[256];      // scan block partials

// ---------------- tf32 helpers ----------------
__device__ __forceinline__ unsigned f2tf32(float f) {
    unsigned r;
    asm("cvt.rna.tf32.f32 %0, %1;" : "=r"(r) : "f"(f));
    return r;
}

__device__ __forceinline__ void mma_tf32(float* c, const unsigned* a,
                                         unsigned b0, unsigned b1) {
    asm volatile(
        "mma.sync.aligned.m16n8k8.row.col.f32.tf32.tf32.f32 "
        "{%0,%1,%2,%3}, {%4,%5,%6,%7}, {%8,%9}, {%0,%1,%2,%3};"
        : "+f"(c[0]), "+f"(c[1]), "+f"(c[2]), "+f"(c[3])
        : "r"(a[0]), "r"(a[1]), "r"(a[2]), "r"(a[3]), "r"(b0), "r"(b1));
}

// ---------------- setup: mean(edge_attr) and c = We . att_e ----------------
__global__ void mean_partial_k(const float* __restrict__ ea) {
    __shared__ float sm[256];
    float sum = 0.f;
    for (int i = blockIdx.x * 256 + threadIdx.x; i < EE; i += 256 * 256)
        sum += ea[i];
    sm[threadIdx.x] = sum;
    __syncthreads();
    for (int o = 128; o; o >>= 1) {
        if (threadIdx.x < o) sm[threadIdx.x] += sm[threadIdx.x + o];
        __syncthreads();
    }
    if (threadIdx.x == 0) g_partial[blockIdx.x] = sm[0];
}

__global__ void setup_scalars_k(const float* __restrict__ We0,
                                const float* __restrict__ ae0,
                                const float* __restrict__ We1,
                                const float* __restrict__ ae1) {
    __shared__ float sm[256];
    int t = threadIdx.x;
    sm[t] = g_partial[t];
    __syncthreads();
    for (int o = 128; o; o >>= 1) {
        if (t < o) sm[t] += sm[t + o];
        __syncthreads();
    }
    if (t == 0) g_scal[0] = sm[0] / (float)EE;
    __syncthreads();
    sm[t] = (t < HH) ? We0[t] * ae0[t] : 0.f;
    __syncthreads();
    for (int o = 128; o; o >>= 1) {
        if (t < o) sm[t] += sm[t + o];
        __syncthreads();
    }
    if (t == 0) g_scal[1] = sm[0];
    __syncthreads();
    sm[t] = (t < HH) ? We1[t] * ae1[t] : 0.f;
    __syncthreads();
    for (int o = 128; o; o >>= 1) {
        if (t < o) sm[t] += sm[t + o];
        __syncthreads();
    }
    if (t == 0) g_scal[2] = sm[0];
}

// ---------------- CSR build ----------------
__global__ void zero_cnt_k() {
    int i = blockIdx.x * blockDim.x + threadIdx.x;
    if (i < NN) g_cnt[i] = 0;
}

__global__ void count_k(const int* __restrict__ ei) {
    int e = blockIdx.x * blockDim.x + threadIdx.x;
    if (e >= ET) return;
    int dst = (e < EE) ? ei[EE + e] : (e - EE);
    atomicAdd(&g_cnt[dst], 1);
}

__global__ void scan1_k() {
    __shared__ int sm[256];
    int t = threadIdx.x;
    int gi = blockIdx.x * 256 + t;
    int v = (gi < NN) ? g_cnt[gi] : 0;
    sm[t] = v;
    __syncthreads();
    for (int o = 1; o < 256; o <<= 1) {
        int add = (t >= o) ? sm[t - o] : 0;
        __syncthreads();
        sm[t] += add;
        __syncthreads();
    }
    if (gi < NN) g_off[gi] = sm[t] - v;
    if (t == 255) g_blksum[blockIdx.x] = sm[255];
}

__global__ void scan2_k(int nblk) {
    __shared__ int sm[256];
    int t = threadIdx.x;
    int v = (t < nblk) ? g_blksum[t] : 0;
    sm[t] = v;
    __syncthreads();
    for (int o = 1; o < 256; o <<= 1) {
        int add = (t >= o) ? sm[t - o] : 0;
        __syncthreads();
        sm[t] += add;
        __syncthreads();
    }
    g_blksum[t] = sm[t] - v;
}

__global__ void scan3_k() {
    int gi = blockIdx.x * blockDim.x + threadIdx.x;
    if (gi < NN) {
        int off = g_off[gi] + g_blksum[gi >> 8];
        g_off[gi] = off;
        g_cnt[gi] = off;
    }
    if (gi == 0) g_off[NN] = ET;
}

__global__ void scatter_k(const int* __restrict__ ei,
                          const float* __restrict__ eattr) {
    int e = blockIdx.x * blockDim.x + threadIdx.x;
    if (e >= ET) return;
    int src, dst; float ea;
    if (e < EE) {
        src = ei[e];
        dst = ei[EE + e];
        ea = eattr[e];
    } else {
        src = dst = e - EE;
        ea = g_scal[0];
    }
    int pos = atomicAdd(&g_cnt[dst], 1);
    g_csrc[pos] = src;
    g_cea[pos] = ea;
}

// ---------------- tensor-core GEMM (3xTF32) + fused attention dots ----------
// C[n][c] = sum_k A[n][k] * W[c][k];  also g_s[n]=C[n]·as, g_d[n]=C[n]·ad
#define SMS 20   // smem k-stride (conflict-free for frag access pattern)
__global__ __launch_bounds__(256) void gemm_tc_k(
    const float* __restrict__ A_ext, int use_hbuf,
    const float* __restrict__ W,
    const float* __restrict__ as, const float* __restrict__ ad) {
    const float* __restrict__ A = use_hbuf ? (const float*)g_hbuf4 : A_ext;
    __shared__ float As_hi[128 * SMS], As_lo[128 * SMS];
    __shared__ float Ws_hi[128 * SMS], Ws_lo[128 * SMS];
    __shared__ float red_s[2][128], red_d[2][128];

    int tid = threadIdx.x;
    int wid = tid >> 5, lane = tid & 31;
    int warp_m = wid >> 1;          // 0..3 -> rows warp_m*32
    int warp_n = wid & 1;           // 0..1 -> cols warp_n*64
    int g = lane >> 2;              // groupID (row within tile)
    int tg = lane & 3;              // thread-in-group (k / col pos)
    int row_blk = blockIdx.x * 128;

    float c[2][8][4];
#pragma unroll
    for (int t = 0; t < 2; t++)
#pragma unroll
        for (int nt = 0; nt < 8; nt++)
#pragma unroll
            for (int j = 0; j < 4; j++) c[t][nt][j] = 0.f;

    for (int kt = 0; kt < 128; kt += 16) {
        // stage A chunk [128 rows x 16 k], split hi/lo
        for (int i = tid; i < 128 * 4; i += 256) {
            int r = i >> 2, q = (i & 3) * 4;
            int gr = row_blk + r;
            float4 v = make_float4(0.f, 0.f, 0.f, 0.f);
            if (gr < NN) v = *(const float4*)&A[gr * 128 + kt + q];
            float h0 = __uint_as_float(f2tf32(v.x));
            float h1 = __uint_as_float(f2tf32(v.y));
            float h2 = __uint_as_float(f2tf32(v.z));
            float h3 = __uint_as_float(f2tf32(v.w));
            int base = r * SMS + q;
            As_hi[base + 0] = h0; As_hi[base + 1] = h1;
            As_hi[base + 2] = h2; As_hi[base + 3] = h3;
            As_lo[base + 0] = __uint_as_float(f2tf32(v.x - h0));
            As_lo[base + 1] = __uint_as_float(f2tf32(v.y - h1));
            As_lo[base + 2] = __uint_as_float(f2tf32(v.z - h2));
            As_lo[base + 3] = __uint_as_float(f2tf32(v.w - h3));
        }
        // stage W chunk [128 cols x 16 k], split hi/lo
        for (int i = tid; i < 128 * 4; i += 256) {
            int cc = i >> 2, q = (i & 3) * 4;
            float4 v = *(const float4*)&W[cc * 128 + kt + q];
            float h0 = __uint_as_float(f2tf32(v.x));
            float h1 = __uint_as_float(f2tf32(v.y));
            float h2 = __uint_as_float(f2tf32(v.z));
            float h3 = __uint_as_float(f2tf32(v.w));
            int base = cc * SMS + q;
            Ws_hi[base + 0] = h0; Ws_hi[base + 1] = h1;
            Ws_hi[base + 2] = h2; Ws_hi[base + 3] = h3;
            Ws_lo[base + 0] = __uint_as_float(f2tf32(v.x - h0));
            Ws_lo[base + 1] = __uint_as_float(f2tf32(v.y - h1));
            Ws_lo[base + 2] = __uint_as_float(f2tf32(v.z - h2));
            Ws_lo[base + 3] = __uint_as_float(f2tf32(v.w - h3));
        }
        __syncthreads();

#pragma unroll
        for (int ks = 0; ks < 16; ks += 8) {
            unsigned ah[2][4], al[2][4];
#pragma unroll
            for (int t = 0; t < 2; t++) {
                int r0 = warp_m * 32 + t * 16;
                int i00 = (r0 + g) * SMS + ks + tg;
                int i10 = (r0 + g + 8) * SMS + ks + tg;
                ah[t][0] = __float_as_uint(As_hi[i00]);
                ah[t][1] = __float_as_uint(As_hi[i10]);
                ah[t][2] = __float_as_uint(As_hi[i00 + 4]);
                ah[t][3] = __float_as_uint(As_hi[i10 + 4]);
                al[t][0] = __float_as_uint(As_lo[i00]);
                al[t][1] = __float_as_uint(As_lo[i10]);
                al[t][2] = __float_as_uint(As_lo[i00 + 4]);
                al[t][3] = __float_as_uint(As_lo[i10 + 4]);
            }
#pragma unroll
            for (int nt = 0; nt < 8; nt++) {
                int c0 = warp_n * 64 + nt * 8;
                int ib = (c0 + g) * SMS + ks + tg;
                unsigned bh0 = __float_as_uint(Ws_hi[ib]);
                unsigned bh1 = __float_as_uint(Ws_hi[ib + 4]);
                unsigned bl0 = __float_as_uint(Ws_lo[ib]);
                unsigned bl1 = __float_as_uint(Ws_lo[ib + 4]);
#pragma unroll
                for (int t = 0; t < 2; t++) {
                    mma_tf32(c[t][nt], ah[t], bh0, bh1);
                    mma_tf32(c[t][nt], ah[t], bl0, bl1);
                    mma_tf32(c[t][nt], al[t], bh0, bh1);
                }
            }
        }
        __syncthreads();
    }

    // epilogue: store hp, compute per-row dots with as/ad
    float* hp = (float*)g_hp4;
    float ps0[2] = {0.f, 0.f}, ps1[2] = {0.f, 0.f};
    float pd0[2] = {0.f, 0.f}, pd1[2] = {0.f, 0.f};
#pragma unroll
    for (int t = 0; t < 2; t++) {
        int r0 = row_blk + warp_m * 32 + t * 16 + g;
#pragma unroll
        for (int nt = 0; nt < 8; nt++) {
            int col = warp_n * 64 + nt * 8 + tg * 2;
            float a0 = as[col], a1 = as[col + 1];
            float d0 = ad[col], d1 = ad[col + 1];
            ps0[t] += c[t][nt][0] * a0 + c[t][nt][1] * a1;
            ps1[t] += c[t][nt][2] * a0 + c[t][nt][3] * a1;
            pd0[t] += c[t][nt][0] * d0 + c[t][nt][1] * d1;
            pd1[t] += c[t][nt][2] * d0 + c[t][nt][3] * d1;
            if (r0 < NN)
                *(float2*)&hp[r0 * 128 + col] = make_float2(c[t][nt][0], c[t][nt][1]);
            if (r0 + 8 < NN)
                *(float2*)&hp[(r0 + 8) * 128 + col] = make_float2(c[t][nt][2], c[t][nt][3]);
        }
    }
    // reduce across the 4 lanes of each group (tg dimension)
#pragma unroll
    for (int t = 0; t < 2; t++) {
#pragma unroll
        for (int o = 1; o < 4; o <<= 1) {
            ps0[t] += __shfl_xor_sync(0xFFFFFFFFu, ps0[t], o);
            ps1[t] += __shfl_xor_sync(0xFFFFFFFFu, ps1[t], o);
            pd0[t] += __shfl_xor_sync(0xFFFFFFFFu, pd0[t], o);
            pd1[t] += __shfl_xor_sync(0xFFFFFFFFu, pd1[t], o);
        }
        if (tg == 0) {
            int lr = warp_m * 32 + t * 16 + g;
            red_s[warp_n][lr] = ps0[t];
            red_s[warp_n][lr + 8] = ps1[t];
            red_d[warp_n][lr] = pd0[t];
            red_d[warp_n][lr + 8] = pd1[t];
        }
    }
    __syncthreads();
    if (tid < 128) {
        int gr = row_blk + tid;
        if (gr < NN) {
            g_s[gr] = red_s[0][tid] + red_s[1][tid];
            g_d[gr] = red_d[0][tid] + red_d[1][tid];
        }
    }
}

// ---------------- warp-per-node single-pass softmax + aggregation -------------
__global__ void agg_k(const float* __restrict__ b, float* __restrict__ out,
                      int layer, int colbase, int writeH) {
    int warp = (blockIdx.x * blockDim.x + threadIdx.x) >> 5;  // exact: NN warps
    int lane = threadIdx.x & 31;
    int n = warp;
    int beg = g_off[n], end = g_off[n + 1];
    float c = g_scal[1 + layer];
    float dterm = g_d[n];

    float4 acc = make_float4(0.f, 0.f, 0.f, 0.f);
    float denom = 0.f;
    for (int i0 = beg; i0 < end; i0 += 32) {
        int i = i0 + lane;
        int src = 0; float w = 0.f;
        if (i < end) {
            src = g_csrc[i];
            float a = g_s[src] + dterm + c * g_cea[i];
            a = (a > 0.f) ? a : NEG * a;
            w = __expf(a);            // softmax is shift-invariant; alpha is O(10)
            denom += w;
        }
        int nvalid = min(32, end - i0);
        for (int j = 0; j < nvalid; j++) {
            float wj = __shfl_sync(0xFFFFFFFFu, w, j);
            int sj = __shfl_sync(0xFFFFFFFFu, src, j);
            float4 v = g_hp4[sj * 32 + lane];
            acc.x += wj * v.x;
            acc.y += wj * v.y;
            acc.z += wj * v.z;
            acc.w += wj * v.w;
        }
    }
#pragma unroll
    for (int o = 16; o; o >>= 1) denom += __shfl_xor_sync(0xFFFFFFFFu, denom, o);

    float inv = 1.0f / (denom + 1e-16f);
    float bx = b[lane * 4 + 0], by = b[lane * 4 + 1],
          bz = b[lane * 4 + 2], bw = b[lane * 4 + 3];
    float ox = fmaxf(acc.x * inv + bx, 0.f);
    float oy = fmaxf(acc.y * inv + by, 0.f);
    float oz = fmaxf(acc.z * inv + bz, 0.f);
    float ow = fmaxf(acc.w * inv + bw, 0.f);
    int base = n * 384 + colbase + lane * 4;
    out[base + 0] = ox;
    out[base + 1] = oy;
    out[base + 2] = oz;
    out[base + 3] = ow;
    if (writeH) g_hbuf4[n * 32 + lane] = make_float4(ox, oy, oz, ow);
}

// ---------------- copy x into first 128 output columns ----------------
__global__ void copy_x_k(const float* __restrict__ x, float* __restrict__ out) {
    int i = blockIdx.x * blockDim.x + threadIdx.x;   // exact: NN*128 threads
    int n = i >> 7, q = i & 127;
    out[n * 384 + q] = x[i];
}

extern "C" void kernel_launch(void* const* d_in, const int* in_sizes, int n_in,
                              void* d_out, int out_size) {
    const float* x   = (const float*)d_in[0];
    const int*   ei  = (const int*)d_in[1];     // int32 [2, E]
    const float* ea  = (const float*)d_in[2];
    const float* W0  = (const float*)d_in[3];
    const float* as0 = (const float*)d_in[4];
    const float* ad0 = (const float*)d_in[5];
    const float* We0 = (const float*)d_in[6];
    const float* ae0 = (const float*)d_in[7];
    const float* b0  = (const float*)d_in[8];
    const float* W1  = (const float*)d_in[9];
    const float* as1 = (const float*)d_in[10];
    const float* ad1 = (const float*)d_in[11];
    const float* We1 = (const float*)d_in[12];
    const float* ae1 = (const float*)d_in[13];
    const float* b1  = (const float*)d_in[14];
    float* out = (float*)d_out;

    const int T = 256;
    const int blkN32  = (NN * 32) / T;            // 6250
    const int blkN128 = (NN * 128) / T;           // 25000
    const int blkN    = (NN + T - 1) / T;         // 196
    const int blkE    = (ET + T - 1) / T;         // 2540
    const int blkG    = (NN + 127) / 128;         // 391

    copy_x_k<<<blkN128, T>>>(x, out);
    mean_partial_k<<<256, T>>>(ea);
    setup_scalars_k<<<1, T>>>(We0, ae0, We1, ae1);

    zero_cnt_k<<<blkN, T>>>();
    count_k<<<blkE, T>>>(ei);
    scan1_k<<<blkN, T>>>();
    scan2_k<<<1, T>>>(blkN);
    scan3_k<<<blkN, T>>>();
    scatter_k<<<blkE, T>>>(ei, ea);

    // ---- layer 0 ----
    gemm_tc_k<<<blkG, T>>>(x, 0, W0, as0, ad0);
    agg_k<<<blkN32, T>>>(b0, out, 0, 128, 1);

    // ---- layer 1 ----
    gemm_tc_k<<<blkG, T>>>(nullptr, 1, W1, as1, ad1);
    agg_k<<<blkN32, T>>>(b1, out, 1, 256, 0);
}

// round 5
// speedup vs baseline: 1.7413x; 1.1959x over previous
#include <cuda_runtime.h>
#include <cuda_fp16.h>
#include <cuda_bf16.h>

#define NN 50000
#define EE 600000
#define ET (EE + NN)   // edges incl. self loops
#define HH 128
#define NEG 0.2f

// ---------------- device scratch (no allocs allowed) ----------------
__device__ uint2  g_hp16[NN * 32];    // layer projection h @ W^T in fp16 (4 vals per uint2)
__device__ float4 g_hbuf4[NN * 32];   // layer-1 output fp32 (input to layer 2 GEMM)
__device__ float  g_s[NN];            // hp . att_src
__device__ float  g_d[NN];            // hp . att_dst
__device__ int    g_cnt[NN];          // degree counts, then scatter cursors
__device__ int    g_off[NN + 1];      // CSR offsets by destination
__device__ int    g_csrc[ET];         // CSR: source node per slot
__device__ float  g_cea[ET];          // CSR: edge_attr scalar per slot
__device__ float  g_scal[4];          // [0]=mean(edge_attr) [1]=c0 [2]=c1
__device__ float  g_partial[256];     // mean reduction partials
__device__ int    g_blksum[256];      // scan block partials

// ---------------- tf32 helpers ----------------
__device__ __forceinline__ unsigned f2tf32(float f) {
    unsigned r;
    asm("cvt.rna.tf32.f32 %0, %1;" : "=r"(r) : "f"(f));
    return r;
}

__device__ __forceinline__ void mma_tf32(float* c, const unsigned* a,
                                         unsigned b0, unsigned b1) {
    asm volatile(
        "mma.sync.aligned.m16n8k8.row.col.f32.tf32.tf32.f32 "
        "{%0,%1,%2,%3}, {%4,%5,%6,%7}, {%8,%9}, {%0,%1,%2,%3};"
        : "+f"(c[0]), "+f"(c[1]), "+f"(c[2]), "+f"(c[3])
        : "r"(a[0]), "r"(a[1]), "r"(a[2]), "r"(a[3]), "r"(b0), "r"(b1));
}

// ---------------- setup: mean(edge_attr) and c = We . att_e ----------------
__global__ void mean_partial_k(const float* __restrict__ ea) {
    __shared__ float sm[256];
    float sum = 0.f;
    for (int i = blockIdx.x * 256 + threadIdx.x; i < EE; i += 256 * 256)
        sum += ea[i];
    sm[threadIdx.x] = sum;
    __syncthreads();
    for (int o = 128; o; o >>= 1) {
        if (threadIdx.x < o) sm[threadIdx.x] += sm[threadIdx.x + o];
        __syncthreads();
    }
    if (threadIdx.x == 0) g_partial[blockIdx.x] = sm[0];
}

__global__ void setup_scalars_k(const float* __restrict__ We0,
                                const float* __restrict__ ae0,
                                const float* __restrict__ We1,
                                const float* __restrict__ ae1) {
    __shared__ float sm[256];
    int t = threadIdx.x;
    sm[t] = g_partial[t];
    __syncthreads();
    for (int o = 128; o; o >>= 1) {
        if (t < o) sm[t] += sm[t + o];
        __syncthreads();
    }
    if (t == 0) g_scal[0] = sm[0] / (float)EE;
    __syncthreads();
    sm[t] = (t < HH) ? We0[t] * ae0[t] : 0.f;
    __syncthreads();
    for (int o = 128; o; o >>= 1) {
        if (t < o) sm[t] += sm[t + o];
        __syncthreads();
    }
    if (t == 0) g_scal[1] = sm[0];
    __syncthreads();
    sm[t] = (t < HH) ? We1[t] * ae1[t] : 0.f;
    __syncthreads();
    for (int o = 128; o; o >>= 1) {
        if (t < o) sm[t] += sm[t + o];
        __syncthreads();
    }
    if (t == 0) g_scal[2] = sm[0];
}

// ---------------- CSR build ----------------
__global__ void zero_cnt_k() {
    int i = blockIdx.x * blockDim.x + threadIdx.x;
    if (i < NN) g_cnt[i] = 0;
}

__global__ void count_k(const int* __restrict__ ei) {
    int e = blockIdx.x * blockDim.x + threadIdx.x;
    if (e >= ET) return;
    int dst = (e < EE) ? ei[EE + e] : (e - EE);
    atomicAdd(&g_cnt[dst], 1);
}

__global__ void scan1_k() {
    __shared__ int sm[256];
    int t = threadIdx.x;
    int gi = blockIdx.x * 256 + t;
    int v = (gi < NN) ? g_cnt[gi] : 0;
    sm[t] = v;
    __syncthreads();
    for (int o = 1; o < 256; o <<= 1) {
        int add = (t >= o) ? sm[t - o] : 0;
        __syncthreads();
        sm[t] += add;
        __syncthreads();
    }
    if (gi < NN) g_off[gi] = sm[t] - v;
    if (t == 255) g_blksum[blockIdx.x] = sm[255];
}

__global__ void scan2_k(int nblk) {
    __shared__ int sm[256];
    int t = threadIdx.x;
    int v = (t < nblk) ? g_blksum[t] : 0;
    sm[t] = v;
    __syncthreads();
    for (int o = 1; o < 256; o <<= 1) {
        int add = (t >= o) ? sm[t - o] : 0;
        __syncthreads();
        sm[t] += add;
        __syncthreads();
    }
    g_blksum[t] = sm[t] - v;
}

__global__ void scan3_k() {
    int gi = blockIdx.x * blockDim.x + threadIdx.x;
    if (gi < NN) {
        int off = g_off[gi] + g_blksum[gi >> 8];
        g_off[gi] = off;
        g_cnt[gi] = off;
    }
    if (gi == 0) g_off[NN] = ET;
}

__global__ void scatter_k(const int* __restrict__ ei,
                          const float* __restrict__ eattr) {
    int e = blockIdx.x * blockDim.x + threadIdx.x;
    if (e >= ET) return;
    int src, dst; float ea;
    if (e < EE) {
        src = ei[e];
        dst = ei[EE + e];
        ea = eattr[e];
    } else {
        src = dst = e - EE;
        ea = g_scal[0];
    }
    int pos = atomicAdd(&g_cnt[dst], 1);
    g_csrc[pos] = src;
    g_cea[pos] = ea;
}

// ---------------- tensor-core GEMM (3xTF32) + fused attention dots ----------
// hp16[n][c] = sum_k A[n][k] * W[c][k] (fp16);  g_s[n]=C[n]·as, g_d[n]=C[n]·ad (fp32)
#define SMS 20
__global__ __launch_bounds__(256) void gemm_tc_k(
    const float* __restrict__ A_ext, int use_hbuf,
    const float* __restrict__ W,
    const float* __restrict__ as, const float* __restrict__ ad) {
    const float* __restrict__ A = use_hbuf ? (const float*)g_hbuf4 : A_ext;
    __shared__ float As_hi[128 * SMS], As_lo[128 * SMS];
    __shared__ float Ws_hi[128 * SMS], Ws_lo[128 * SMS];
    __shared__ float red_s[2][128], red_d[2][128];

    int tid = threadIdx.x;
    int wid = tid >> 5, lane = tid & 31;
    int warp_m = wid >> 1;
    int warp_n = wid & 1;
    int g = lane >> 2;
    int tg = lane & 3;
    int row_blk = blockIdx.x * 128;

    float c[2][8][4];
#pragma unroll
    for (int t = 0; t < 2; t++)
#pragma unroll
        for (int nt = 0; nt < 8; nt++)
#pragma unroll
            for (int j = 0; j < 4; j++) c[t][nt][j] = 0.f;

    for (int kt = 0; kt < 128; kt += 16) {
        for (int i = tid; i < 128 * 4; i += 256) {
            int r = i >> 2, q = (i & 3) * 4;
            int gr = row_blk + r;
            float4 v = make_float4(0.f, 0.f, 0.f, 0.f);
            if (gr < NN) v = *(const float4*)&A[gr * 128 + kt + q];
            float h0 = __uint_as_float(f2tf32(v.x));
            float h1 = __uint_as_float(f2tf32(v.y));
            float h2 = __uint_as_float(f2tf32(v.z));
            float h3 = __uint_as_float(f2tf32(v.w));
            int base = r * SMS + q;
            As_hi[base + 0] = h0; As_hi[base + 1] = h1;
            As_hi[base + 2] = h2; As_hi[base + 3] = h3;
            As_lo[base + 0] = __uint_as_float(f2tf32(v.x - h0));
            As_lo[base + 1] = __uint_as_float(f2tf32(v.y - h1));
            As_lo[base + 2] = __uint_as_float(f2tf32(v.z - h2));
            As_lo[base + 3] = __uint_as_float(f2tf32(v.w - h3));
        }
        for (int i = tid; i < 128 * 4; i += 256) {
            int cc = i >> 2, q = (i & 3) * 4;
            float4 v = *(const float4*)&W[cc * 128 + kt + q];
            float h0 = __uint_as_float(f2tf32(v.x));
            float h1 = __uint_as_float(f2tf32(v.y));
            float h2 = __uint_as_float(f2tf32(v.z));
            float h3 = __uint_as_float(f2tf32(v.w));
            int base = cc * SMS + q;
            Ws_hi[base + 0] = h0; Ws_hi[base + 1] = h1;
            Ws_hi[base + 2] = h2; Ws_hi[base + 3] = h3;
            Ws_lo[base + 0] = __uint_as_float(f2tf32(v.x - h0));
            Ws_lo[base + 1] = __uint_as_float(f2tf32(v.y - h1));
            Ws_lo[base + 2] = __uint_as_float(f2tf32(v.z - h2));
            Ws_lo[base + 3] = __uint_as_float(f2tf32(v.w - h3));
        }
        __syncthreads();

#pragma unroll
        for (int ks = 0; ks < 16; ks += 8) {
            unsigned ah[2][4], al[2][4];
#pragma unroll
            for (int t = 0; t < 2; t++) {
                int r0 = warp_m * 32 + t * 16;
                int i00 = (r0 + g) * SMS + ks + tg;
                int i10 = (r0 + g + 8) * SMS + ks + tg;
                ah[t][0] = __float_as_uint(As_hi[i00]);
                ah[t][1] = __float_as_uint(As_hi[i10]);
                ah[t][2] = __float_as_uint(As_hi[i00 + 4]);
                ah[t][3] = __float_as_uint(As_hi[i10 + 4]);
                al[t][0] = __float_as_uint(As_lo[i00]);
                al[t][1] = __float_as_uint(As_lo[i10]);
                al[t][2] = __float_as_uint(As_lo[i00 + 4]);
                al[t][3] = __float_as_uint(As_lo[i10 + 4]);
            }
#pragma unroll
            for (int nt = 0; nt < 8; nt++) {
                int c0 = warp_n * 64 + nt * 8;
                int ib = (c0 + g) * SMS + ks + tg;
                unsigned bh0 = __float_as_uint(Ws_hi[ib]);
                unsigned bh1 = __float_as_uint(Ws_hi[ib + 4]);
                unsigned bl0 = __float_as_uint(Ws_lo[ib]);
                unsigned bl1 = __float_as_uint(Ws_lo[ib + 4]);
#pragma unroll
                for (int t = 0; t < 2; t++) {
                    mma_tf32(c[t][nt], ah[t], bh0, bh1);
                    mma_tf32(c[t][nt], ah[t], bl0, bl1);
                    mma_tf32(c[t][nt], al[t], bh0, bh1);
                }
            }
        }
        __syncthreads();
    }

    // epilogue: fp16 hp store + per-row attention dots
    __half2* hp = (__half2*)g_hp16;
    float ps0[2] = {0.f, 0.f}, ps1[2] = {0.f, 0.f};
    float pd0[2] = {0.f, 0.f}, pd1[2] = {0.f, 0.f};
#pragma unroll
    for (int t = 0; t < 2; t++) {
        int r0 = row_blk + warp_m * 32 + t * 16 + g;
#pragma unroll
        for (int nt = 0; nt < 8; nt++) {
            int col = warp_n * 64 + nt * 8 + tg * 2;
            float a0 = as[col], a1 = as[col + 1];
            float d0 = ad[col], d1 = ad[col + 1];
            ps0[t] += c[t][nt][0] * a0 + c[t][nt][1] * a1;
            ps1[t] += c[t][nt][2] * a0 + c[t][nt][3] * a1;
            pd0[t] += c[t][nt][0] * d0 + c[t][nt][1] * d1;
            pd1[t] += c[t][nt][2] * d0 + c[t][nt][3] * d1;
            if (r0 < NN)
                hp[r0 * 64 + (col >> 1)] = __floats2half2_rn(c[t][nt][0], c[t][nt][1]);
            if (r0 + 8 < NN)
                hp[(r0 + 8) * 64 + (col >> 1)] = __floats2half2_rn(c[t][nt][2], c[t][nt][3]);
        }
    }
#pragma unroll
    for (int t = 0; t < 2; t++) {
#pragma unroll
        for (int o = 1; o < 4; o <<= 1) {
            ps0[t] += __shfl_xor_sync(0xFFFFFFFFu, ps0[t], o);
            ps1[t] += __shfl_xor_sync(0xFFFFFFFFu, ps1[t], o);
            pd0[t] += __shfl_xor_sync(0xFFFFFFFFu, pd0[t], o);
            pd1[t] += __shfl_xor_sync(0xFFFFFFFFu, pd1[t], o);
        }
        if (tg == 0) {
            int lr = warp_m * 32 + t * 16 + g;
            red_s[warp_n][lr] = ps0[t];
            red_s[warp_n][lr + 8] = ps1[t];
            red_d[warp_n][lr] = pd0[t];
            red_d[warp_n][lr + 8] = pd1[t];
        }
    }
    __syncthreads();
    if (tid < 128) {
        int gr = row_blk + tid;
        if (gr < NN) {
            g_s[gr] = red_s[0][tid] + red_s[1][tid];
            g_d[gr] = red_d[0][tid] + red_d[1][tid];
        }
    }
}

// ---------------- warp-per-node single-pass softmax + fp16 gather -------------
__global__ __launch_bounds__(256) void agg_k(
    const float* __restrict__ b, float* __restrict__ out,
    int layer, int colbase, int writeH) {
    __shared__ float sw[8][32];
    __shared__ int   ssrc[8][32];
    int warp = (blockIdx.x * blockDim.x + threadIdx.x) >> 5;  // exact: NN warps
    int lane = threadIdx.x & 31;
    int ws = (threadIdx.x >> 5) & 7;
    int n = warp;
    int beg = g_off[n], end = g_off[n + 1];
    float c = g_scal[1 + layer];
    float dterm = g_d[n];

    float4 acc = make_float4(0.f, 0.f, 0.f, 0.f);
    float denom = 0.f;
    for (int i0 = beg; i0 < end; i0 += 32) {
        int i = i0 + lane;
        int src = 0; float w = 0.f;
        if (i < end) {
            src = g_csrc[i];
            float a = g_s[src] + dterm + c * g_cea[i];
            a = (a > 0.f) ? a : NEG * a;
            w = __expf(a);            // softmax shift-invariant; alpha is O(10)
            denom += w;
        }
        sw[ws][lane] = w;
        ssrc[ws][lane] = src;
        __syncwarp();
        int nvalid = min(32, end - i0);
#pragma unroll 4
        for (int j = 0; j < nvalid; j++) {
            float wj = sw[ws][j];
            uint2 p = g_hp16[ssrc[ws][j] * 32 + lane];
            float2 lo = __half22float2(*(__half2*)&p.x);
            float2 hi = __half22float2(*(__half2*)&p.y);
            acc.x += wj * lo.x;
            acc.y += wj * lo.y;
            acc.z += wj * hi.x;
            acc.w += wj * hi.y;
        }
        __syncwarp();
    }
#pragma unroll
    for (int o = 16; o; o >>= 1) denom += __shfl_xor_sync(0xFFFFFFFFu, denom, o);

    float inv = 1.0f / (denom + 1e-16f);
    float bx = b[lane * 4 + 0], by = b[lane * 4 + 1],
          bz = b[lane * 4 + 2], bw = b[lane * 4 + 3];
    float ox = fmaxf(acc.x * inv + bx, 0.f);
    float oy = fmaxf(acc.y * inv + by, 0.f);
    float oz = fmaxf(acc.z * inv + bz, 0.f);
    float ow = fmaxf(acc.w * inv + bw, 0.f);
    int base = n * 384 + colbase + lane * 4;
    out[base + 0] = ox;
    out[base + 1] = oy;
    out[base + 2] = oz;
    out[base + 3] = ow;
    if (writeH) g_hbuf4[n * 32 + lane] = make_float4(ox, oy, oz, ow);
}

// ---------------- copy x into first 128 output columns (vectorized) -----------
__global__ void copy_x_k(const float4* __restrict__ x4, float* __restrict__ out) {
    int i = blockIdx.x * blockDim.x + threadIdx.x;   // exact: NN*32 threads
    int n = i >> 5, q = i & 31;
    *(float4*)&out[n * 384 + q * 4] = x4[i];
}

extern "C" void kernel_launch(void* const* d_in, const int* in_sizes, int n_in,
                              void* d_out, int out_size) {
    const float* x   = (const float*)d_in[0];
    const int*   ei  = (const int*)d_in[1];     // int32 [2, E]
    const float* ea  = (const float*)d_in[2];
    const float* W0  = (const float*)d_in[3];
    const float* as0 = (const float*)d_in[4];
    const float* ad0 = (const float*)d_in[5];
    const float* We0 = (const float*)d_in[6];
    const float* ae0 = (const float*)d_in[7];
    const float* b0  = (const float*)d_in[8];
    const float* W1  = (const float*)d_in[9];
    const float* as1 = (const float*)d_in[10];
    const float* ad1 = (const float*)d_in[11];
    const float* We1 = (const float*)d_in[12];
    const float* ae1 = (const float*)d_in[13];
    const float* b1  = (const float*)d_in[14];
    float* out = (float*)d_out;

    const int T = 256;
    const int blkN32  = (NN * 32) / T;            // 6250
    const int blkN    = (NN + T - 1) / T;         // 196
    const int blkE    = (ET + T - 1) / T;         // 2540
    const int blkG    = (NN + 127) / 128;         // 391

    copy_x_k<<<blkN32, T>>>((const float4*)x, out);
    mean_partial_k<<<256, T>>>(ea);
    setup_scalars_k<<<1, T>>>(We0, ae0, We1, ae1);

    zero_cnt_k<<<blkN, T>>>();
    count_k<<<blkE, T>>>(ei);
    scan1_k<<<blkN, T>>>();
    scan2_k<<<1, T>>>(blkN);
    scan3_k<<<blkN, T>>>();
    scatter_k<<<blkE, T>>>(ei, ea);

    // ---- layer 0 ----
    gemm_tc_k<<<blkG, T>>>(x, 0, W0, as0, ad0);
    agg_k<<<blkN32, T>>>(b0, out, 0, 128, 1);

    // ---- layer 1 ----
    gemm_tc_k<<<blkG, T>>>(nullptr, 1, W1, as1, ad1);
    agg_k<<<blkN32, T>>>(b1, out, 1, 256, 0);
}